// round 12
// baseline (speedup 1.0000x reference)
#include <cuda_runtime.h>

typedef unsigned long long ull;

// Chain state: 4-channel fields only. h1 ping-pong, h2 stored per block.
__device__ float g_h1[2][16][4][64][64];   //  2.1 MB
__device__ float g_h2[32][16][4][64][64];  // 33.6 MB

// ---- packed fp32x2 helpers --------------------------------------------------
__device__ __forceinline__ ull ffma2(ull a, ull b, ull c) {
    ull d; asm("fma.rn.f32x2 %0, %1, %2, %3;" : "=l"(d) : "l"(a), "l"(b), "l"(c)); return d;
}
__device__ __forceinline__ ull fadd2(ull a, ull b) {
    ull d; asm("add.rn.f32x2 %0, %1, %2;" : "=l"(d) : "l"(a), "l"(b)); return d;
}
__device__ __forceinline__ ull pack2(float lo, float hi) {
    ull d; asm("mov.b64 %0, {%1, %2};" : "=l"(d) : "f"(lo), "f"(hi)); return d;
}
__device__ __forceinline__ ull dup2(float v) { return pack2(v, v); }
__device__ __forceinline__ ull relu2(ull z) {
    float lo, hi; asm("mov.b64 {%0, %1}, %2;" : "=f"(lo), "=f"(hi) : "l"(z));
    return pack2(fmaxf(lo, 0.f), fmaxf(hi, 0.f));
}
__device__ __forceinline__ ull packmid(ull a, ull b) {
    float alo, ahi, blo, bhi;
    asm("mov.b64 {%0, %1}, %2;" : "=f"(alo), "=f"(ahi) : "l"(a));
    asm("mov.b64 {%0, %1}, %2;" : "=f"(blo), "=f"(bhi) : "l"(b));
    return pack2(ahi, blo);
}

// ---------------------------------------------------------------------------
// k0: h1_0 = relu(W1_0 @ x + b1_0).  Memory-bound (reads x, 67MB).
// ---------------------------------------------------------------------------
__global__ __launch_bounds__(256) void k0_kernel(const float* __restrict__ x,
                                                 const float* __restrict__ w1,
                                                 const float* __restrict__ b1) {
    __shared__ float4 sW1T[256];
    __shared__ float  sB1[4];
    int tid = threadIdx.x;
    if (tid < 4) sB1[tid] = b1[tid];
    sW1T[tid] = make_float4(w1[tid], w1[256 + tid], w1[512 + tid], w1[768 + tid]);
    __syncthreads();

    int n  = blockIdx.x >> 4;
    int yg = blockIdx.x & 15;
    int px = tid & 63;
    int y  = yg * 4 + (tid >> 6);

    const float* xp = x + (size_t)n * 256 * 4096 + y * 64 + px;
    float a0 = sB1[0], a1 = sB1[1], a2 = sB1[2], a3 = sB1[3];
#pragma unroll 8
    for (int c = 0; c < 256; c++) {
        float  xv = xp[c * 4096];
        float4 w  = sW1T[c];
        a0 = fmaf(xv, w.x, a0);
        a1 = fmaf(xv, w.y, a1);
        a2 = fmaf(xv, w.z, a2);
        a3 = fmaf(xv, w.w, a3);
    }
    float* hp = &g_h1[0][n][0][y][px];
    hp[0]     = fmaxf(a0, 0.f);
    hp[4096]  = fmaxf(a1, 0.f);
    hp[8192]  = fmaxf(a2, 0.f);
    hp[12288] = fmaxf(a3, 0.f);
}

// ---------------------------------------------------------------------------
// chain_kernel (block i): CHANNEL-PACKED fused loop.
//   grid 256 = 16 img x 16 tiles (16x16); 256 threads.
//   Conv: threads 0..127, one pixel-pair each (full 4-ch conv, pixel-packed),
//         u written to s_u (smem) + h2 (gmem).
//   Fused: 256 threads = 64 slots (4 px each) x 4 quarters (64 ch each).
//         f32x2 lanes = adjacent CHANNELS -> weights packed naturally in smem
//         (NO duplication: 5 LDS per 2 channels serve 4 pixels).
//         Quarter partials combined via 2 butterfly shuffles (no smem).
// ---------------------------------------------------------------------------
__global__ __launch_bounds__(256, 2) void chain_kernel(
    const float* __restrict__ w1, const float* __restrict__ b1,
    const float* __restrict__ w2, const float* __restrict__ b2,
    const float* __restrict__ w3, const float* __restrict__ b3,
    int blk)
{
    __shared__ __align__(16) float s_h1[4][18][18];
    __shared__ ull        s_w2d[144];      // dup-packed conv weights [j][k][dy][dx]
    __shared__ float      s_b2[4];
    __shared__ ulonglong2 s_w3p[128][2];   // [m]: lanes {c=2m, 2m+1}; [0]={j0,j1} [1]={j2,j3}
    __shared__ ulonglong2 s_w1p[128][2];   // [m]: {w1[j][2m], w1[j][2m+1]} pairs
    __shared__ ull        s_b3p[128];      // {b3[2m], b3[2m+1]}
    __shared__ float      s_b1n[4];
    __shared__ __align__(16) float s_u[4][256];  // conv output, linear px in tile

    int tid  = threadIdx.x;
    int n    = blockIdx.x >> 4;
    int tile = blockIdx.x & 15;
    int ty0  = (tile >> 2) * 16;
    int tx0  = (tile & 3)  * 16;

    // ---- weight staging ----
    if (tid < 144) s_w2d[tid] = dup2(w2[blk * 144 + tid]);
    else if (tid < 148) s_b2[tid - 144] = b2[blk * 4 + (tid - 144)];
    else if (tid < 152 && blk < 31) s_b1n[tid - 148] = b1[(blk + 1) * 4 + (tid - 148)];
    if (blk < 31 && tid < 128) {
        int m = tid;
        const float* w3r = &w3[((size_t)blk * 256 + 2 * m) * 4];
        float4 ra = *(const float4*)w3r;
        float4 rb = *(const float4*)(w3r + 4);
        s_w3p[m][0] = make_ulonglong2(pack2(ra.x, rb.x), pack2(ra.y, rb.y));
        s_w3p[m][1] = make_ulonglong2(pack2(ra.z, rb.z), pack2(ra.w, rb.w));
        const float* w1n = w1 + (blk + 1) * 1024;
        s_w1p[m][0] = make_ulonglong2(pack2(w1n[2 * m],       w1n[2 * m + 1]),
                                      pack2(w1n[256 + 2 * m], w1n[256 + 2 * m + 1]));
        s_w1p[m][1] = make_ulonglong2(pack2(w1n[512 + 2 * m], w1n[512 + 2 * m + 1]),
                                      pack2(w1n[768 + 2 * m], w1n[768 + 2 * m + 1]));
        s_b3p[m] = pack2(b3[blk * 256 + 2 * m], b3[blk * 256 + 2 * m + 1]);
    }

    // ---- halo tile load: 18x18x4 (zero pad = SAME padding) ----
    const float* h1base = &g_h1[blk & 1][n][0][0][0];
    for (int idx = tid; idx < 324; idx += 256) {
        int yy = idx / 18, xx = idx % 18;
        int gy = ty0 + yy - 1, gx = tx0 + xx - 1;
        bool ok = (gy >= 0 && gy < 64 && gx >= 0 && gx < 64);
#pragma unroll
        for (int k = 0; k < 4; k++)
            s_h1[k][yy][xx] = ok ? h1base[k * 4096 + gy * 64 + gx] : 0.f;
    }
    __syncthreads();

    // ---- conv3x3: threads 0..127, one pixel-pair each, ALL 4 input channels ----
    if (tid < 128) {
        int pair = tid;
        int py = pair >> 3;
        int x0 = (pair & 7) * 2;
        ull r0 = dup2(s_b2[0]), r1 = dup2(s_b2[1]), r2 = dup2(s_b2[2]), r3 = dup2(s_b2[3]);
#pragma unroll
        for (int k = 0; k < 4; k++) {
#pragma unroll
            for (int dy = 0; dy < 3; dy++) {
                const ull* rowp = (const ull*)&s_h1[k][py + dy][x0];
                ull p01 = rowp[0], p23 = rowp[1];
                ull t0 = p01, t1 = packmid(p01, p23), t2 = p23;
                int wi = k * 9 + dy * 3;
                r0 = ffma2(t0, s_w2d[wi + 0], r0);
                r1 = ffma2(t0, s_w2d[36 + wi + 0], r1);
                r2 = ffma2(t0, s_w2d[72 + wi + 0], r2);
                r3 = ffma2(t0, s_w2d[108 + wi + 0], r3);
                r0 = ffma2(t1, s_w2d[wi + 1], r0);
                r1 = ffma2(t1, s_w2d[36 + wi + 1], r1);
                r2 = ffma2(t1, s_w2d[72 + wi + 1], r2);
                r3 = ffma2(t1, s_w2d[108 + wi + 1], r3);
                r0 = ffma2(t2, s_w2d[wi + 2], r0);
                r1 = ffma2(t2, s_w2d[36 + wi + 2], r1);
                r2 = ffma2(t2, s_w2d[72 + wi + 2], r2);
                r3 = ffma2(t2, s_w2d[108 + wi + 2], r3);
            }
        }
        ull u0 = relu2(r0), u1 = relu2(r1), u2 = relu2(r2), u3 = relu2(r3);

        int gy = ty0 + py, gx = tx0 + x0;
        ull* hp = (ull*)&g_h2[blk][n][0][gy][gx];   // ch stride = 2048 ull
        hp[0] = u0; hp[2048] = u1; hp[4096] = u2; hp[6144] = u3;

        *(ull*)&s_u[0][2 * pair] = u0;
        *(ull*)&s_u[1][2 * pair] = u1;
        *(ull*)&s_u[2][2 * pair] = u2;
        *(ull*)&s_u[3][2 * pair] = u3;
    }
    __syncthreads();

    // ---- fused 4->256->4 composite, channel-packed ----
    if (blk < 31) {
        int slot = tid >> 2;        // 0..63: 4 pixels p0..p0+3
        int q    = tid & 3;         // channel quarter (lane bits 0-1 within warp)
        int p0   = slot * 4;

        float4 uu0 = *(const float4*)&s_u[0][p0];
        float4 uu1 = *(const float4*)&s_u[1][p0];
        float4 uu2 = *(const float4*)&s_u[2][p0];
        float4 uu3 = *(const float4*)&s_u[3][p0];

        ull ud[4][4];   // [px][j] duplicated u
        ud[0][0] = dup2(uu0.x); ud[0][1] = dup2(uu1.x); ud[0][2] = dup2(uu2.x); ud[0][3] = dup2(uu3.x);
        ud[1][0] = dup2(uu0.y); ud[1][1] = dup2(uu1.y); ud[1][2] = dup2(uu2.y); ud[1][3] = dup2(uu3.y);
        ud[2][0] = dup2(uu0.z); ud[2][1] = dup2(uu1.z); ud[2][2] = dup2(uu2.z); ud[2][3] = dup2(uu3.z);
        ud[3][0] = dup2(uu0.w); ud[3][1] = dup2(uu1.w); ud[3][2] = dup2(uu2.w); ud[3][3] = dup2(uu3.w);

        ull ap[4][4];   // [px][j] channel-pair-packed accumulators
#pragma unroll
        for (int k2 = 0; k2 < 4; k2++)
#pragma unroll
            for (int j = 0; j < 4; j++) ap[k2][j] = 0ull;

        int m0 = q << 5;
#pragma unroll 4
        for (int mm = 0; mm < 32; mm++) {
            int m = m0 + mm;
            ulonglong2 w3a = s_w3p[m][0], w3b = s_w3p[m][1];
            ulonglong2 w1a = s_w1p[m][0], w1b = s_w1p[m][1];
            ull bb = s_b3p[m];
#pragma unroll
            for (int k2 = 0; k2 < 4; k2++) {
                ull z = ffma2(ud[k2][0], w3a.x, bb);
                z = ffma2(ud[k2][1], w3a.y, z);
                z = ffma2(ud[k2][2], w3b.x, z);
                z = ffma2(ud[k2][3], w3b.y, z);
                ull v = relu2(z);
                ap[k2][0] = ffma2(v, w1a.x, ap[k2][0]);
                ap[k2][1] = ffma2(v, w1a.y, ap[k2][1]);
                ap[k2][2] = ffma2(v, w1b.x, ap[k2][2]);
                ap[k2][3] = ffma2(v, w1b.y, ap[k2][3]);
            }
        }

        // horizontal add (channel lanes) + butterfly reduce over the 4 quarters
        float res[4][4];
#pragma unroll
        for (int k2 = 0; k2 < 4; k2++) {
#pragma unroll
            for (int j = 0; j < 4; j++) {
                float lo, hi;
                asm("mov.b64 {%0, %1}, %2;" : "=f"(lo), "=f"(hi) : "l"(ap[k2][j]));
                float r = lo + hi;
                r += __shfl_xor_sync(0xffffffffu, r, 1);
                r += __shfl_xor_sync(0xffffffffu, r, 2);
                res[k2][j] = r;
            }
        }

        // lane (slot,q) writes channel q for its 4 consecutive pixels
        float bq = s_b1n[q];
        int row = slot >> 2;            // p0>>4
        int colb = (slot & 3) * 4;      // p0&15, multiple of 4 -> 16B aligned
        float* hp = &g_h1[(blk + 1) & 1][n][q][ty0 + row][tx0 + colb];
        float4 o;
        o.x = fmaxf(res[0][q] + bq, 0.f);
        o.y = fmaxf(res[1][q] + bq, 0.f);
        o.z = fmaxf(res[2][q] + bq, 0.f);
        o.w = fmaxf(res[3][q] + bq, 0.f);
        *(float4*)hp = o;
    }
}

// ---------------------------------------------------------------------------
// acc_kernel: out = sum_i relu(W3_i @ h2_i + b3_i)  (R8 form — ~55% of peak)
// Grid 1024 (16 img x 64 rows), 256 threads = 16 dual-slots x 16 ch-groups.
// ---------------------------------------------------------------------------
__global__ __launch_bounds__(256) void acc_kernel(const float* __restrict__ w3,
                                                  const float* __restrict__ b3,
                                                  float* __restrict__ out) {
    __shared__ ulonglong2 s_w3d[256][2];
    __shared__ ull        s_b3d[256];
    __shared__ __align__(16) float s_u[4][64];

    int tid   = threadIdx.x;
    int n     = blockIdx.x >> 6;
    int y     = blockIdx.x & 63;
    int dual  = tid & 15;
    int grp   = tid >> 4;
    int pxA   = dual * 2;
    int pxB   = pxA + 32;
    int cbase = grp * 16;

    ull accA[16], accB[16];
#pragma unroll
    for (int cc = 0; cc < 16; cc++) { accA[cc] = 0ull; accB[cc] = 0ull; }

    for (int i = 0; i < 32; i++) {
        __syncthreads();
        float4 wr = *(const float4*)&w3[(i * 256 + tid) * 4];
        s_w3d[tid][0] = make_ulonglong2(dup2(wr.x), dup2(wr.y));
        s_w3d[tid][1] = make_ulonglong2(dup2(wr.z), dup2(wr.w));
        s_b3d[tid]    = dup2(b3[i * 256 + tid]);
        s_u[tid >> 6][tid & 63] = g_h2[i][n][tid >> 6][y][tid & 63];
        __syncthreads();

        ull uA0 = *(const ull*)&s_u[0][pxA];
        ull uA1 = *(const ull*)&s_u[1][pxA];
        ull uA2 = *(const ull*)&s_u[2][pxA];
        ull uA3 = *(const ull*)&s_u[3][pxA];
        ull uB0 = *(const ull*)&s_u[0][pxB];
        ull uB1 = *(const ull*)&s_u[1][pxB];
        ull uB2 = *(const ull*)&s_u[2][pxB];
        ull uB3 = *(const ull*)&s_u[3][pxB];
#pragma unroll
        for (int cc = 0; cc < 16; cc++) {
            int c = cbase + cc;
            ulonglong2 wA = s_w3d[c][0], wB = s_w3d[c][1];
            ull bb = s_b3d[c];
            ull zA = ffma2(uA0, wA.x, bb);
            zA = ffma2(uA1, wA.y, zA);
            zA = ffma2(uA2, wB.x, zA);
            zA = ffma2(uA3, wB.y, zA);
            accA[cc] = fadd2(accA[cc], relu2(zA));
            ull zB = ffma2(uB0, wA.x, bb);
            zB = ffma2(uB1, wA.y, zB);
            zB = ffma2(uB2, wB.x, zB);
            zB = ffma2(uB3, wB.y, zB);
            accB[cc] = fadd2(accB[cc], relu2(zB));
        }
    }

#pragma unroll
    for (int cc = 0; cc < 16; cc++) {
        int c = cbase + cc;
        size_t base = (((size_t)n * 256 + c) * 64 + y) * 64;
        *(ull*)&out[base + pxA] = accA[cc];
        *(ull*)&out[base + pxB] = accB[cc];
    }
}

// ---------------------------------------------------------------------------
extern "C" void kernel_launch(void* const* d_in, const int* in_sizes, int n_in,
                              void* d_out, int out_size) {
    const float* x  = (const float*)d_in[0];
    const float* w1 = (const float*)d_in[1];
    const float* b1 = (const float*)d_in[2];
    const float* w2 = (const float*)d_in[3];
    const float* b2 = (const float*)d_in[4];
    const float* w3 = (const float*)d_in[5];
    const float* b3 = (const float*)d_in[6];
    float* out = (float*)d_out;

    k0_kernel<<<256, 256>>>(x, w1, b1);
    for (int i = 0; i < 32; i++)
        chain_kernel<<<256, 256>>>(w1, b1, w2, b2, w3, b3, i);
    acc_kernel<<<1024, 256>>>(w3, b3, out);
}

// round 13
// speedup vs baseline: 1.5202x; 1.5202x over previous
#include <cuda_runtime.h>

typedef unsigned long long ull;

// Chain state: 4-channel fields only. h1 ping-pong, h2 stored per block.
__device__ float g_h1[2][16][4][64][64];   //  2.1 MB
__device__ float g_h2[32][16][4][64][64];  // 33.6 MB

// ---- packed fp32x2 helpers --------------------------------------------------
__device__ __forceinline__ ull ffma2(ull a, ull b, ull c) {
    ull d; asm("fma.rn.f32x2 %0, %1, %2, %3;" : "=l"(d) : "l"(a), "l"(b), "l"(c)); return d;
}
__device__ __forceinline__ ull fadd2(ull a, ull b) {
    ull d; asm("add.rn.f32x2 %0, %1, %2;" : "=l"(d) : "l"(a), "l"(b)); return d;
}
__device__ __forceinline__ ull pack2(float lo, float hi) {
    ull d; asm("mov.b64 %0, {%1, %2};" : "=l"(d) : "f"(lo), "f"(hi)); return d;
}
__device__ __forceinline__ ull dup2(float v) { return pack2(v, v); }
__device__ __forceinline__ ull relu2(ull z) {
    float lo, hi; asm("mov.b64 {%0, %1}, %2;" : "=f"(lo), "=f"(hi) : "l"(z));
    return pack2(fmaxf(lo, 0.f), fmaxf(hi, 0.f));
}
__device__ __forceinline__ ull packmid(ull a, ull b) {
    float alo, ahi, blo, bhi;
    asm("mov.b64 {%0, %1}, %2;" : "=f"(alo), "=f"(ahi) : "l"(a));
    asm("mov.b64 {%0, %1}, %2;" : "=f"(blo), "=f"(bhi) : "l"(b));
    return pack2(ahi, blo);
}

// ---------------------------------------------------------------------------
// k0: h1_0 = relu(W1_0 @ x + b1_0).  Memory-bound (reads x, 67MB).
// ---------------------------------------------------------------------------
__global__ __launch_bounds__(256) void k0_kernel(const float* __restrict__ x,
                                                 const float* __restrict__ w1,
                                                 const float* __restrict__ b1) {
    __shared__ float4 sW1T[256];
    __shared__ float  sB1[4];
    int tid = threadIdx.x;
    if (tid < 4) sB1[tid] = b1[tid];
    sW1T[tid] = make_float4(w1[tid], w1[256 + tid], w1[512 + tid], w1[768 + tid]);
    __syncthreads();

    int n  = blockIdx.x >> 4;
    int yg = blockIdx.x & 15;
    int px = tid & 63;
    int y  = yg * 4 + (tid >> 6);

    const float* xp = x + (size_t)n * 256 * 4096 + y * 64 + px;
    float a0 = sB1[0], a1 = sB1[1], a2 = sB1[2], a3 = sB1[3];
#pragma unroll 8
    for (int c = 0; c < 256; c++) {
        float  xv = xp[c * 4096];
        float4 w  = sW1T[c];
        a0 = fmaf(xv, w.x, a0);
        a1 = fmaf(xv, w.y, a1);
        a2 = fmaf(xv, w.z, a2);
        a3 = fmaf(xv, w.w, a3);
    }
    float* hp = &g_h1[0][n][0][y][px];
    hp[0]     = fmaxf(a0, 0.f);
    hp[4096]  = fmaxf(a1, 0.f);
    hp[8192]  = fmaxf(a2, 0.f);
    hp[12288] = fmaxf(a3, 0.f);
}

// ---------------------------------------------------------------------------
// chain_kernel (block i): CHANNEL-PACKED fused loop, CONFLICT-FREE layout.
//   Weight arrays interleaved [mm][q] so the 4 quarter-lanes of a warp read
//   addresses 32B apart (banks 0-3/8-11/16-19/24-27) instead of 1024B apart.
//   Channel pair m = 4*mm + q  (bijection; sum over channels is invariant).
// ---------------------------------------------------------------------------
__global__ __launch_bounds__(256, 2) void chain_kernel(
    const float* __restrict__ w1, const float* __restrict__ b1,
    const float* __restrict__ w2, const float* __restrict__ b2,
    const float* __restrict__ w3, const float* __restrict__ b3,
    int blk)
{
    __shared__ __align__(16) float s_h1[4][18][18];
    __shared__ ull        s_w2d[144];        // dup-packed conv weights [j][k][dy][dx]
    __shared__ float      s_b2[4];
    __shared__ ulonglong2 s_w3p[32][4][2];   // [mm][q]: channel pair m=4mm+q, {j0j1, j2j3}
    __shared__ ulonglong2 s_w1p[32][4][2];   // [mm][q]: w1 column pairs
    __shared__ ull        s_b3p[32][4];      // [mm][q]: {b3[2m], b3[2m+1]}
    __shared__ float      s_b1n[4];
    __shared__ __align__(16) float s_u[4][256];  // conv output, linear px in tile

    int tid  = threadIdx.x;
    int n    = blockIdx.x >> 4;
    int tile = blockIdx.x & 15;
    int ty0  = (tile >> 2) * 16;
    int tx0  = (tile & 3)  * 16;

    // ---- weight staging ----
    if (tid < 144) s_w2d[tid] = dup2(w2[blk * 144 + tid]);
    else if (tid < 148) s_b2[tid - 144] = b2[blk * 4 + (tid - 144)];
    else if (tid < 152 && blk < 31) s_b1n[tid - 148] = b1[(blk + 1) * 4 + (tid - 148)];
    if (blk < 31 && tid < 128) {
        int m  = tid;            // channel pair index: channels 2m, 2m+1
        int mm = m >> 2, qs = m & 3;
        const float* w3r = &w3[((size_t)blk * 256 + 2 * m) * 4];
        float4 ra = *(const float4*)w3r;
        float4 rb = *(const float4*)(w3r + 4);
        s_w3p[mm][qs][0] = make_ulonglong2(pack2(ra.x, rb.x), pack2(ra.y, rb.y));
        s_w3p[mm][qs][1] = make_ulonglong2(pack2(ra.z, rb.z), pack2(ra.w, rb.w));
        const float* w1n = w1 + (blk + 1) * 1024;
        s_w1p[mm][qs][0] = make_ulonglong2(pack2(w1n[2 * m],       w1n[2 * m + 1]),
                                           pack2(w1n[256 + 2 * m], w1n[256 + 2 * m + 1]));
        s_w1p[mm][qs][1] = make_ulonglong2(pack2(w1n[512 + 2 * m], w1n[512 + 2 * m + 1]),
                                           pack2(w1n[768 + 2 * m], w1n[768 + 2 * m + 1]));
        s_b3p[mm][qs] = pack2(b3[blk * 256 + 2 * m], b3[blk * 256 + 2 * m + 1]);
    }

    // ---- halo tile load: 18x18x4 (zero pad = SAME padding) ----
    const float* h1base = &g_h1[blk & 1][n][0][0][0];
    for (int idx = tid; idx < 324; idx += 256) {
        int yy = idx / 18, xx = idx % 18;
        int gy = ty0 + yy - 1, gx = tx0 + xx - 1;
        bool ok = (gy >= 0 && gy < 64 && gx >= 0 && gx < 64);
#pragma unroll
        for (int k = 0; k < 4; k++)
            s_h1[k][yy][xx] = ok ? h1base[k * 4096 + gy * 64 + gx] : 0.f;
    }
    __syncthreads();

    // ---- conv3x3: threads 0..127, one pixel-pair each, ALL 4 input channels ----
    if (tid < 128) {
        int pair = tid;
        int py = pair >> 3;
        int x0 = (pair & 7) * 2;
        ull r0 = dup2(s_b2[0]), r1 = dup2(s_b2[1]), r2 = dup2(s_b2[2]), r3 = dup2(s_b2[3]);
#pragma unroll
        for (int k = 0; k < 4; k++) {
#pragma unroll
            for (int dy = 0; dy < 3; dy++) {
                const ull* rowp = (const ull*)&s_h1[k][py + dy][x0];
                ull p01 = rowp[0], p23 = rowp[1];
                ull t0 = p01, t1 = packmid(p01, p23), t2 = p23;
                int wi = k * 9 + dy * 3;
                r0 = ffma2(t0, s_w2d[wi + 0], r0);
                r1 = ffma2(t0, s_w2d[36 + wi + 0], r1);
                r2 = ffma2(t0, s_w2d[72 + wi + 0], r2);
                r3 = ffma2(t0, s_w2d[108 + wi + 0], r3);
                r0 = ffma2(t1, s_w2d[wi + 1], r0);
                r1 = ffma2(t1, s_w2d[36 + wi + 1], r1);
                r2 = ffma2(t1, s_w2d[72 + wi + 1], r2);
                r3 = ffma2(t1, s_w2d[108 + wi + 1], r3);
                r0 = ffma2(t2, s_w2d[wi + 2], r0);
                r1 = ffma2(t2, s_w2d[36 + wi + 2], r1);
                r2 = ffma2(t2, s_w2d[72 + wi + 2], r2);
                r3 = ffma2(t2, s_w2d[108 + wi + 2], r3);
            }
        }
        ull u0 = relu2(r0), u1 = relu2(r1), u2 = relu2(r2), u3 = relu2(r3);

        int gy = ty0 + py, gx = tx0 + x0;
        ull* hp = (ull*)&g_h2[blk][n][0][gy][gx];   // ch stride = 2048 ull
        hp[0] = u0; hp[2048] = u1; hp[4096] = u2; hp[6144] = u3;

        *(ull*)&s_u[0][2 * pair] = u0;
        *(ull*)&s_u[1][2 * pair] = u1;
        *(ull*)&s_u[2][2 * pair] = u2;
        *(ull*)&s_u[3][2 * pair] = u3;
    }
    __syncthreads();

    // ---- fused 4->256->4 composite, channel-packed, conflict-free ----
    if (blk < 31) {
        int slot = tid >> 2;        // 0..63: 4 pixels p0..p0+3
        int q    = tid & 3;         // quarter (lane bits 0-1 within warp)
        int p0   = slot * 4;

        float4 uu0 = *(const float4*)&s_u[0][p0];
        float4 uu1 = *(const float4*)&s_u[1][p0];
        float4 uu2 = *(const float4*)&s_u[2][p0];
        float4 uu3 = *(const float4*)&s_u[3][p0];

        ull ud[4][4];   // [px][j] duplicated u
        ud[0][0] = dup2(uu0.x); ud[0][1] = dup2(uu1.x); ud[0][2] = dup2(uu2.x); ud[0][3] = dup2(uu3.x);
        ud[1][0] = dup2(uu0.y); ud[1][1] = dup2(uu1.y); ud[1][2] = dup2(uu2.y); ud[1][3] = dup2(uu3.y);
        ud[2][0] = dup2(uu0.z); ud[2][1] = dup2(uu1.z); ud[2][2] = dup2(uu2.z); ud[2][3] = dup2(uu3.z);
        ud[3][0] = dup2(uu0.w); ud[3][1] = dup2(uu1.w); ud[3][2] = dup2(uu2.w); ud[3][3] = dup2(uu3.w);

        ull ap[4][4];   // [px][j] channel-pair-packed accumulators
#pragma unroll
        for (int k2 = 0; k2 < 4; k2++)
#pragma unroll
            for (int j = 0; j < 4; j++) ap[k2][j] = 0ull;

#pragma unroll 4
        for (int mm = 0; mm < 32; mm++) {
            ulonglong2 w3a = s_w3p[mm][q][0], w3b = s_w3p[mm][q][1];
            ulonglong2 w1a = s_w1p[mm][q][0], w1b = s_w1p[mm][q][1];
            ull bb = s_b3p[mm][q];
#pragma unroll
            for (int k2 = 0; k2 < 4; k2++) {
                ull z = ffma2(ud[k2][0], w3a.x, bb);
                z = ffma2(ud[k2][1], w3a.y, z);
                z = ffma2(ud[k2][2], w3b.x, z);
                z = ffma2(ud[k2][3], w3b.y, z);
                ull v = relu2(z);
                ap[k2][0] = ffma2(v, w1a.x, ap[k2][0]);
                ap[k2][1] = ffma2(v, w1a.y, ap[k2][1]);
                ap[k2][2] = ffma2(v, w1b.x, ap[k2][2]);
                ap[k2][3] = ffma2(v, w1b.y, ap[k2][3]);
            }
        }

        // horizontal add (channel lanes) + butterfly reduce over the 4 quarters
        float res[4][4];
#pragma unroll
        for (int k2 = 0; k2 < 4; k2++) {
#pragma unroll
            for (int j = 0; j < 4; j++) {
                float lo, hi;
                asm("mov.b64 {%0, %1}, %2;" : "=f"(lo), "=f"(hi) : "l"(ap[k2][j]));
                float r = lo + hi;
                r += __shfl_xor_sync(0xffffffffu, r, 1);
                r += __shfl_xor_sync(0xffffffffu, r, 2);
                res[k2][j] = r;
            }
        }

        // lane (slot,q) writes channel q for its 4 consecutive pixels
        float bq = s_b1n[q];
        int row = slot >> 2;            // p0>>4
        int colb = (slot & 3) * 4;      // p0&15, multiple of 4 -> 16B aligned
        float* hp = &g_h1[(blk + 1) & 1][n][q][ty0 + row][tx0 + colb];
        float4 o;
        o.x = fmaxf(res[0][q] + bq, 0.f);
        o.y = fmaxf(res[1][q] + bq, 0.f);
        o.z = fmaxf(res[2][q] + bq, 0.f);
        o.w = fmaxf(res[3][q] + bq, 0.f);
        *(float4*)hp = o;
    }
}

// ---------------------------------------------------------------------------
// acc_kernel: out = sum_i relu(W3_i @ h2_i + b3_i)
// R8 form + skewed weight index (c + (c>>4)) to kill the 2-way bank conflict
// between half-warps (c vs c+16 were 512B apart = same banks).
// ---------------------------------------------------------------------------
__global__ __launch_bounds__(256) void acc_kernel(const float* __restrict__ w3,
                                                  const float* __restrict__ b3,
                                                  float* __restrict__ out) {
    __shared__ ulonglong2 s_w3d[272][2];   // skewed: idx = c + (c>>4)
    __shared__ ull        s_b3d[272];
    __shared__ __align__(16) float s_u[4][64];

    int tid   = threadIdx.x;
    int n     = blockIdx.x >> 6;
    int y     = blockIdx.x & 63;
    int dual  = tid & 15;
    int grp   = tid >> 4;
    int pxA   = dual * 2;
    int pxB   = pxA + 32;
    int cbase = grp * 16;

    ull accA[16], accB[16];
#pragma unroll
    for (int cc = 0; cc < 16; cc++) { accA[cc] = 0ull; accB[cc] = 0ull; }

    for (int i = 0; i < 32; i++) {
        __syncthreads();
        float4 wr = *(const float4*)&w3[(i * 256 + tid) * 4];
        int sk = tid + (tid >> 4);
        s_w3d[sk][0] = make_ulonglong2(dup2(wr.x), dup2(wr.y));
        s_w3d[sk][1] = make_ulonglong2(dup2(wr.z), dup2(wr.w));
        s_b3d[sk]    = dup2(b3[i * 256 + tid]);
        s_u[tid >> 6][tid & 63] = g_h2[i][n][tid >> 6][y][tid & 63];
        __syncthreads();

        ull uA0 = *(const ull*)&s_u[0][pxA];
        ull uA1 = *(const ull*)&s_u[1][pxA];
        ull uA2 = *(const ull*)&s_u[2][pxA];
        ull uA3 = *(const ull*)&s_u[3][pxA];
        ull uB0 = *(const ull*)&s_u[0][pxB];
        ull uB1 = *(const ull*)&s_u[1][pxB];
        ull uB2 = *(const ull*)&s_u[2][pxB];
        ull uB3 = *(const ull*)&s_u[3][pxB];
        int skbase = cbase + grp;   // skew of cbase (cbase>>4 == grp)
#pragma unroll
        for (int cc = 0; cc < 16; cc++) {
            int c = skbase + cc;
            ulonglong2 wA = s_w3d[c][0], wB = s_w3d[c][1];
            ull bb = s_b3d[c];
            ull zA = ffma2(uA0, wA.x, bb);
            zA = ffma2(uA1, wA.y, zA);
            zA = ffma2(uA2, wB.x, zA);
            zA = ffma2(uA3, wB.y, zA);
            accA[cc] = fadd2(accA[cc], relu2(zA));
            ull zB = ffma2(uB0, wA.x, bb);
            zB = ffma2(uB1, wA.y, zB);
            zB = ffma2(uB2, wB.x, zB);
            zB = ffma2(uB3, wB.y, zB);
            accB[cc] = fadd2(accB[cc], relu2(zB));
        }
    }

#pragma unroll
    for (int cc = 0; cc < 16; cc++) {
        int c = cbase + cc;
        size_t base = (((size_t)n * 256 + c) * 64 + y) * 64;
        *(ull*)&out[base + pxA] = accA[cc];
        *(ull*)&out[base + pxB] = accB[cc];
    }
}

// ---------------------------------------------------------------------------
extern "C" void kernel_launch(void* const* d_in, const int* in_sizes, int n_in,
                              void* d_out, int out_size) {
    const float* x  = (const float*)d_in[0];
    const float* w1 = (const float*)d_in[1];
    const float* b1 = (const float*)d_in[2];
    const float* w2 = (const float*)d_in[3];
    const float* b2 = (const float*)d_in[4];
    const float* w3 = (const float*)d_in[5];
    const float* b3 = (const float*)d_in[6];
    float* out = (float*)d_out;

    k0_kernel<<<256, 256>>>(x, w1, b1);
    for (int i = 0; i < 32; i++)
        chain_kernel<<<256, 256>>>(w1, b1, w2, b2, w3, b3, i);
    acc_kernel<<<1024, 256>>>(w3, b3, out);
}